// round 1
// baseline (speedup 1.0000x reference)
#include <cuda_runtime.h>
#include <cuda_bf16.h>
#include <math.h>

// ---------------- problem constants ----------------
#define NN 50000
#define EE 400000
// layer dims: L0 in=128 -> 4x64 (res GEMM), L1 256->4x64 (identity res), L2 256->4x40 (res GEMM)

// ---------------- scratch (static device globals; no allocation allowed) ----------------
__device__ float g_hs[NN * 256];
__device__ float g_hd[NN * 256];
__device__ float g_res[NN * 256];
__device__ float g_xA[NN * 256];
__device__ float g_xB[NN * 256];
__device__ int   g_deg[NN];
__device__ int   g_cur[NN];
__device__ int   g_off[NN + 1];
__device__ int   g_ssrc[EE];
__device__ int   g_bsum[64];

// ---------------- CSR build ----------------
__global__ void k_zero(int n) {
    int i = blockIdx.x * 256 + threadIdx.x;
    if (i < n) { g_deg[i] = 0; g_cur[i] = 0; }
}

__global__ void k_hist(const int* __restrict__ dst, int E) {
    int i = blockIdx.x * 256 + threadIdx.x;
    if (i < E) atomicAdd(&g_deg[dst[i]], 1);
}

__global__ void k_scan_reduce(int n) {
    __shared__ int sm[1024];
    int tid = threadIdx.x;
    int i = blockIdx.x * 1024 + tid;
    sm[tid] = (i < n) ? g_deg[i] : 0;
    __syncthreads();
    for (int st = 512; st > 0; st >>= 1) {
        if (tid < st) sm[tid] += sm[tid + st];
        __syncthreads();
    }
    if (tid == 0) g_bsum[blockIdx.x] = sm[0];
}

__global__ void k_scan_bsum(int nb, int n, int E) {
    int run = 0;
    for (int b = 0; b < nb; b++) { int t = g_bsum[b]; g_bsum[b] = run; run += t; }
    g_off[n] = E;
}

__global__ void k_scan_final(int n) {
    __shared__ int sm[1024];
    int tid = threadIdx.x;
    int i = blockIdx.x * 1024 + tid;
    int v = (i < n) ? g_deg[i] : 0;
    sm[tid] = v;
    __syncthreads();
    for (int st = 1; st < 1024; st <<= 1) {
        int t = (tid >= st) ? sm[tid - st] : 0;
        __syncthreads();
        sm[tid] += t;
        __syncthreads();
    }
    if (i < n) g_off[i] = g_bsum[blockIdx.x] + sm[tid] - v;
}

__global__ void k_scatter(const int* __restrict__ src, const int* __restrict__ dst, int E) {
    int i = blockIdx.x * 256 + threadIdx.x;
    if (i < E) {
        int d = dst[i];
        int p = g_off[d] + atomicAdd(&g_cur[d], 1);
        g_ssrc[p] = src[i];
    }
}

// ---------------- GEMM: C[M,NC] = X[M,K] @ W[K,NC] + b ----------------
// BM=128 BN=128 BK=8, 256 threads, 8x8 per thread.
__global__ void __launch_bounds__(256) gemm_bias(
    const float* __restrict__ X, const float* __restrict__ W,
    const float* __restrict__ bias, float* __restrict__ C,
    int M, int K, int NC)
{
    __shared__ float Xs[8][128];
    __shared__ float Ws[8][128];
    const int tid = threadIdx.x;
    const int bm = blockIdx.x * 128;
    const int bn = blockIdx.y * 128;
    const int tr = (tid >> 4) * 8;    // 0..120 row base in tile
    const int tc = (tid & 15) * 8;    // 0..120 col base in tile
    const int lxr = tid >> 1;         // 0..127
    const int lxc = (tid & 1) * 4;    // 0 or 4
    const int lwr = tid >> 5;         // 0..7
    const int lwc = (tid & 31) * 4;   // 0..124

    float acc[8][8];
#pragma unroll
    for (int i = 0; i < 8; i++)
#pragma unroll
        for (int j = 0; j < 8; j++) acc[i][j] = 0.f;

    const int grow = bm + lxr;
    const bool xok = grow < M;
    const int gcol = bn + lwc;
    const bool wok = gcol < NC;  // NC % 4 == 0 so whole float4 valid

    for (int k0 = 0; k0 < K; k0 += 8) {
        float4 xv = make_float4(0.f, 0.f, 0.f, 0.f);
        if (xok) xv = *(const float4*)(X + (size_t)grow * K + k0 + lxc);
        Xs[lxc + 0][lxr] = xv.x;
        Xs[lxc + 1][lxr] = xv.y;
        Xs[lxc + 2][lxr] = xv.z;
        Xs[lxc + 3][lxr] = xv.w;
        float4 wv = make_float4(0.f, 0.f, 0.f, 0.f);
        if (wok) wv = *(const float4*)(W + (size_t)(k0 + lwr) * NC + gcol);
        *(float4*)&Ws[lwr][lwc] = wv;
        __syncthreads();
#pragma unroll
        for (int kk = 0; kk < 8; kk++) {
            float xr[8], wr[8];
#pragma unroll
            for (int i = 0; i < 8; i++) xr[i] = Xs[kk][tr + i];
#pragma unroll
            for (int j = 0; j < 8; j++) wr[j] = Ws[kk][tc + j];
#pragma unroll
            for (int i = 0; i < 8; i++)
#pragma unroll
                for (int j = 0; j < 8; j++) acc[i][j] += xr[i] * wr[j];
        }
        __syncthreads();
    }
#pragma unroll
    for (int i = 0; i < 8; i++) {
        int r = bm + tr + i;
        if (r < M) {
#pragma unroll
            for (int j = 0; j < 8; j += 4) {
                int c = bn + tc + j;
                if (c < NC) {
                    float4 o;
                    o.x = acc[i][j + 0] + bias[c + 0];
                    o.y = acc[i][j + 1] + bias[c + 1];
                    o.z = acc[i][j + 2] + bias[c + 2];
                    o.w = acc[i][j + 3] + bias[c + 3];
                    *(float4*)(C + (size_t)r * NC + c) = o;
                }
            }
        }
    }
}

// ---------------- edge kernels (warp per dst node, online softmax) ----------------
__device__ __forceinline__ float lrelu(float t) { return t > 0.f ? t : 0.2f * t; }
__device__ __forceinline__ float lrdot(float4 h, float4 d, float4 a) {
    return lrelu(h.x + d.x) * a.x + lrelu(h.y + d.y) * a.y +
           lrelu(h.z + d.z) * a.z + lrelu(h.w + d.w) * a.w;
}

// D=64, H=4, H*D=256. lane l owns elems [4l..4l+3] (head l>>4) and [128+4l..128+4l+3] (head 2+(l>>4)).
__global__ void __launch_bounds__(256) gat_edge_d64(
    const float* __restrict__ hs, const float* __restrict__ hd,
    const float* __restrict__ attn, const float* __restrict__ res,
    float* __restrict__ xout, int N)
{
    int w = (blockIdx.x * blockDim.x + threadIdx.x) >> 5;
    if (w >= N) return;
    int lane = threadIdx.x & 31;
    int i1 = 4 * lane, i2 = 128 + 4 * lane;
    size_t nb = (size_t)w * 256;
    float4 a1 = *(const float4*)(attn + i1);
    float4 a2 = *(const float4*)(attn + i2);
    float4 d1 = *(const float4*)(hd + nb + i1);
    float4 d2 = *(const float4*)(hd + nb + i2);
    float m1 = -1e30f, s1 = 0.f, m2 = -1e30f, s2 = 0.f;
    float4 c1 = make_float4(0.f, 0.f, 0.f, 0.f);
    float4 c2 = make_float4(0.f, 0.f, 0.f, 0.f);
    int e0 = g_off[w], e1 = g_off[w + 1];
    for (int e = e0; e < e1; e++) {
        int sn = g_ssrc[e];
        const float* hp = hs + (size_t)sn * 256;
        float4 h1 = *(const float4*)(hp + i1);
        float4 h2 = *(const float4*)(hp + i2);
        float p1 = lrdot(h1, d1, a1);
        float p2 = lrdot(h2, d2, a2);
#pragma unroll
        for (int o = 8; o; o >>= 1) {
            p1 += __shfl_xor_sync(0xffffffffu, p1, o);
            p2 += __shfl_xor_sync(0xffffffffu, p2, o);
        }
        float nm = fmaxf(m1, p1);
        float sc = __expf(m1 - nm), wt = __expf(p1 - nm);
        s1 = s1 * sc + wt;
        c1.x = c1.x * sc + wt * h1.x; c1.y = c1.y * sc + wt * h1.y;
        c1.z = c1.z * sc + wt * h1.z; c1.w = c1.w * sc + wt * h1.w;
        m1 = nm;
        nm = fmaxf(m2, p2);
        sc = __expf(m2 - nm); wt = __expf(p2 - nm);
        s2 = s2 * sc + wt;
        c2.x = c2.x * sc + wt * h2.x; c2.y = c2.y * sc + wt * h2.y;
        c2.z = c2.z * sc + wt * h2.z; c2.w = c2.w * sc + wt * h2.w;
        m2 = nm;
    }
    float v1 = (s1 > 0.f) ? 1.f / s1 : 0.f;
    float v2 = (s2 > 0.f) ? 1.f / s2 : 0.f;
    float4 r1 = *(const float4*)(res + nb + i1);
    float4 r2 = *(const float4*)(res + nb + i2);
    float4 o1, o2;
    o1.x = c1.x * v1 + r1.x; o1.y = c1.y * v1 + r1.y;
    o1.z = c1.z * v1 + r1.z; o1.w = c1.w * v1 + r1.w;
    o2.x = c2.x * v2 + r2.x; o2.y = c2.y * v2 + r2.y;
    o2.z = c2.z * v2 + r2.z; o2.w = c2.w * v2 + r2.w;
    *(float4*)(xout + nb + i1) = o1;
    *(float4*)(xout + nb + i2) = o2;
}

// D=40, H=4 (160 per node). lane: head = lane>>3, dims (lane&7)*5..+4. Fuses residual + head-mean -> out[N,40].
__global__ void __launch_bounds__(256) gat_edge_d40(
    const float* __restrict__ hs, const float* __restrict__ hd,
    const float* __restrict__ attn, const float* __restrict__ res,
    float* __restrict__ out, int N)
{
    int w = (blockIdx.x * blockDim.x + threadIdx.x) >> 5;
    if (w >= N) return;
    int lane = threadIdx.x & 31;
    int h = lane >> 3;
    int d0 = (lane & 7) * 5;
    int idx = h * 40 + d0;
    float a[5], dv[5];
#pragma unroll
    for (int j = 0; j < 5; j++) {
        a[j] = attn[idx + j];
        dv[j] = hd[(size_t)w * 160 + idx + j];
    }
    float m = -1e30f, s = 0.f;
    float acc[5] = {0.f, 0.f, 0.f, 0.f, 0.f};
    int e0 = g_off[w], e1 = g_off[w + 1];
    for (int e = e0; e < e1; e++) {
        int sn = g_ssrc[e];
        const float* hp = hs + (size_t)sn * 160 + idx;
        float hv[5];
#pragma unroll
        for (int j = 0; j < 5; j++) hv[j] = hp[j];
        float p = 0.f;
#pragma unroll
        for (int j = 0; j < 5; j++) p += lrelu(hv[j] + dv[j]) * a[j];
#pragma unroll
        for (int o = 4; o; o >>= 1) p += __shfl_xor_sync(0xffffffffu, p, o);
        float nm = fmaxf(m, p);
        float sc = __expf(m - nm), wt = __expf(p - nm);
        s = s * sc + wt;
#pragma unroll
        for (int j = 0; j < 5; j++) acc[j] = acc[j] * sc + wt * hv[j];
        m = nm;
    }
    float inv = (s > 0.f) ? 1.f / s : 0.f;
    float v[5];
#pragma unroll
    for (int j = 0; j < 5; j++) v[j] = acc[j] * inv + res[(size_t)w * 160 + idx + j];
    // mean over 4 heads (lanes l, l^8, l^16, l^24 hold the 4 heads for same dims)
#pragma unroll
    for (int j = 0; j < 5; j++) {
        v[j] += __shfl_xor_sync(0xffffffffu, v[j], 8);
        v[j] += __shfl_xor_sync(0xffffffffu, v[j], 16);
    }
    if (lane < 8) {
#pragma unroll
        for (int j = 0; j < 5; j++) out[(size_t)w * 40 + d0 + j] = 0.25f * v[j];
    }
}

// ---------------- launch ----------------
extern "C" void kernel_launch(void* const* d_in, const int* in_sizes, int n_in,
                              void* d_out, int out_size)
{
    const float* x0  = (const float*)d_in[0];
    const int*   src = (const int*)d_in[1];
    const int*   dst = (const int*)d_in[2];
    const float* ws0 = (const float*)d_in[3];
    const float* bs0 = (const float*)d_in[4];
    const float* wd0 = (const float*)d_in[5];
    const float* bd0 = (const float*)d_in[6];
    const float* at0 = (const float*)d_in[7];
    const float* wr0 = (const float*)d_in[8];
    const float* br0 = (const float*)d_in[9];
    const float* ws1 = (const float*)d_in[10];
    const float* bs1 = (const float*)d_in[11];
    const float* wd1 = (const float*)d_in[12];
    const float* bd1 = (const float*)d_in[13];
    const float* at1 = (const float*)d_in[14];
    const float* ws2 = (const float*)d_in[15];
    const float* bs2 = (const float*)d_in[16];
    const float* wd2 = (const float*)d_in[17];
    const float* bd2 = (const float*)d_in[18];
    const float* at2 = (const float*)d_in[19];
    const float* wr2 = (const float*)d_in[20];
    const float* br2 = (const float*)d_in[21];
    float* out = (float*)d_out;

    const int N = NN, E = EE;

    float *hs, *hd, *res, *xA, *xB;
    cudaGetSymbolAddress((void**)&hs,  g_hs);
    cudaGetSymbolAddress((void**)&hd,  g_hd);
    cudaGetSymbolAddress((void**)&res, g_res);
    cudaGetSymbolAddress((void**)&xA,  g_xA);
    cudaGetSymbolAddress((void**)&xB,  g_xB);

    // CSR by dst
    k_zero<<<(N + 255) / 256, 256>>>(N);
    k_hist<<<(E + 255) / 256, 256>>>(dst, E);
    int NB = (N + 1023) / 1024;
    k_scan_reduce<<<NB, 1024>>>(N);
    k_scan_bsum<<<1, 1>>>(NB, N, E);
    k_scan_final<<<NB, 1024>>>(N);
    k_scatter<<<(E + 255) / 256, 256>>>(src, dst, E);

    const int MB = (N + 127) / 128;
    const int ewarps = (N * 32 + 255) / 256;

    // layer 0: K=128, NC=256, linear residual
    {
        dim3 g(MB, 2);
        gemm_bias<<<g, 256>>>(x0, ws0, bs0, hs, N, 128, 256);
        gemm_bias<<<g, 256>>>(x0, wd0, bd0, hd, N, 128, 256);
        gemm_bias<<<g, 256>>>(x0, wr0, br0, res, N, 128, 256);
        gat_edge_d64<<<ewarps, 256>>>(hs, hd, at0, res, xA, N);
    }
    // layer 1: K=256, NC=256, identity residual (xA)
    {
        dim3 g(MB, 2);
        gemm_bias<<<g, 256>>>(xA, ws1, bs1, hs, N, 256, 256);
        gemm_bias<<<g, 256>>>(xA, wd1, bd1, hd, N, 256, 256);
        gat_edge_d64<<<ewarps, 256>>>(hs, hd, at1, xA, xB, N);
    }
    // layer 2: K=256, NC=160, linear residual, fused head-mean -> out
    {
        dim3 g(MB, 2);  // ceil(160/128) = 2
        gemm_bias<<<g, 256>>>(xB, ws2, bs2, hs, N, 256, 160);
        gemm_bias<<<g, 256>>>(xB, wd2, bd2, hd, N, 256, 160);
        gemm_bias<<<g, 256>>>(xB, wr2, br2, res, N, 256, 160);
        gat_edge_d40<<<ewarps, 256>>>(hs, hd, at2, res, out, N);
    }
}

// round 2
// speedup vs baseline: 1.3565x; 1.3565x over previous
#include <cuda_runtime.h>
#include <cuda_bf16.h>
#include <math.h>
#include <stdint.h>

// ---------------- problem constants ----------------
#define NN 50000
#define EE 400000

// ---------------- scratch (static device globals; no allocation allowed) ----------------
__device__ float g_hs[NN * 256];
__device__ float g_hd[NN * 256];
__device__ float g_res[NN * 256];
__device__ float g_xA[NN * 256];
__device__ float g_xB[NN * 256];
__device__ int   g_deg[NN];
__device__ int   g_cur[NN];
__device__ int   g_off[NN + 1];
__device__ int   g_ssrc[EE];
__device__ int   g_bsum[64];

// ---------------- CSR build ----------------
__global__ void k_zero(int n) {
    int i = blockIdx.x * 256 + threadIdx.x;
    if (i < n) { g_deg[i] = 0; g_cur[i] = 0; }
}

__global__ void k_hist(const int* __restrict__ dst, int E) {
    int i = blockIdx.x * 256 + threadIdx.x;
    if (i < E) atomicAdd(&g_deg[dst[i]], 1);
}

__global__ void k_scan_reduce(int n) {
    __shared__ int sm[1024];
    int tid = threadIdx.x;
    int i = blockIdx.x * 1024 + tid;
    sm[tid] = (i < n) ? g_deg[i] : 0;
    __syncthreads();
    for (int st = 512; st > 0; st >>= 1) {
        if (tid < st) sm[tid] += sm[tid + st];
        __syncthreads();
    }
    if (tid == 0) g_bsum[blockIdx.x] = sm[0];
}

__global__ void k_scan_bsum(int nb, int n, int E) {
    int run = 0;
    for (int b = 0; b < nb; b++) { int t = g_bsum[b]; g_bsum[b] = run; run += t; }
    g_off[n] = E;
}

__global__ void k_scan_final(int n) {
    __shared__ int sm[1024];
    int tid = threadIdx.x;
    int i = blockIdx.x * 1024 + tid;
    int v = (i < n) ? g_deg[i] : 0;
    sm[tid] = v;
    __syncthreads();
    for (int st = 1; st < 1024; st <<= 1) {
        int t = (tid >= st) ? sm[tid - st] : 0;
        __syncthreads();
        sm[tid] += t;
        __syncthreads();
    }
    if (i < n) g_off[i] = g_bsum[blockIdx.x] + sm[tid] - v;
}

__global__ void k_scatter(const int* __restrict__ src, const int* __restrict__ dst, int E) {
    int i = blockIdx.x * 256 + threadIdx.x;
    if (i < E) {
        int d = dst[i];
        int p = g_off[d] + atomicAdd(&g_cur[d], 1);
        g_ssrc[p] = src[i];
    }
}

// ---------------- tf32 tensor-core GEMM ----------------
// C[M,NC] = X[M,K] @ W[K,NC] + bias.  BM=BN=128, BK=16, 256 threads (8 warps).
// Warp tile 64x32 via mma.sync.m16n8k8 tf32 (4 row-frags x 4 col-frags).
// SMEM layout [k][m]/[k][n] with stride 136 (136 % 32 == 8 -> the four tg
// groups hit disjoint bank octets -> conflict-free fragment LDS).

__device__ __forceinline__ uint32_t f2tf32(float f) {
    uint32_t u;
    asm("cvt.rna.tf32.f32 %0, %1;" : "=r"(u) : "f"(f));
    return u;
}

__device__ __forceinline__ void mma_tf32(float* c, const uint32_t* a, const uint32_t* b) {
    asm volatile(
        "mma.sync.aligned.m16n8k8.row.col.f32.tf32.tf32.f32 "
        "{%0,%1,%2,%3}, {%4,%5,%6,%7}, {%8,%9}, {%0,%1,%2,%3};\n"
        : "+f"(c[0]), "+f"(c[1]), "+f"(c[2]), "+f"(c[3])
        : "r"(a[0]), "r"(a[1]), "r"(a[2]), "r"(a[3]), "r"(b[0]), "r"(b[1]));
}

__global__ void __launch_bounds__(256) gemm_tf32(
    const float* __restrict__ X, const float* __restrict__ W,
    const float* __restrict__ bias, float* __restrict__ C,
    int M, int K, int NC)
{
    __shared__ uint32_t Xs[16][136];
    __shared__ uint32_t Ws[16][136];
    const int tid  = threadIdx.x;
    const int lane = tid & 31;
    const int wid  = tid >> 5;
    const int wr   = (wid & 1) * 64;   // warp row base in tile
    const int wc   = (wid >> 1) * 32;  // warp col base in tile
    const int bm   = blockIdx.x * 128;
    const int bn   = blockIdx.y * 128;
    const int g    = lane >> 2;        // groupID (0..7)
    const int tg   = lane & 3;         // thread-in-group (0..3)

    float acc[4][4][4];
#pragma unroll
    for (int i = 0; i < 4; i++)
#pragma unroll
        for (int j = 0; j < 4; j++)
#pragma unroll
            for (int k = 0; k < 4; k++) acc[i][j][k] = 0.f;

    for (int k0 = 0; k0 < K; k0 += 16) {
        // Stage X tile (128 rows x 16 k) -> Xs[k][m], tf32-converted, transposed.
#pragma unroll
        for (int i = 0; i < 2; i++) {
            int f   = tid * 2 + i;       // 0..511
            int row = f >> 2;            // 0..127
            int kc  = (f & 3) * 4;       // 0,4,8,12
            float4 v = make_float4(0.f, 0.f, 0.f, 0.f);
            if (bm + row < M)
                v = *(const float4*)(X + (size_t)(bm + row) * K + k0 + kc);
            Xs[kc + 0][row] = f2tf32(v.x);
            Xs[kc + 1][row] = f2tf32(v.y);
            Xs[kc + 2][row] = f2tf32(v.z);
            Xs[kc + 3][row] = f2tf32(v.w);
        }
        // Stage W tile (16 k x 128 n) -> Ws[k][n], tf32-converted.
#pragma unroll
        for (int i = 0; i < 2; i++) {
            int f = tid * 2 + i;
            int k = f >> 5;              // 0..15
            int c = (f & 31) * 4;        // 0..124
            float4 v = make_float4(0.f, 0.f, 0.f, 0.f);
            if (bn + c < NC)             // NC % 4 == 0 -> whole float4 valid
                v = *(const float4*)(W + (size_t)(k0 + k) * NC + bn + c);
            uint4 u;
            u.x = f2tf32(v.x); u.y = f2tf32(v.y);
            u.z = f2tf32(v.z); u.w = f2tf32(v.w);
            *(uint4*)&Ws[k][c] = u;
        }
        __syncthreads();

#pragma unroll
        for (int ks = 0; ks < 2; ks++) {
            uint32_t a[4][4], b[4][2];
#pragma unroll
            for (int fr = 0; fr < 4; fr++) {
                int r = wr + fr * 16;
                a[fr][0] = Xs[ks * 8 + tg    ][r + g    ];
                a[fr][1] = Xs[ks * 8 + tg    ][r + g + 8];
                a[fr][2] = Xs[ks * 8 + tg + 4][r + g    ];
                a[fr][3] = Xs[ks * 8 + tg + 4][r + g + 8];
            }
#pragma unroll
            for (int fc = 0; fc < 4; fc++) {
                int c = wc + fc * 8;
                b[fc][0] = Ws[ks * 8 + tg    ][c + g];
                b[fc][1] = Ws[ks * 8 + tg + 4][c + g];
            }
#pragma unroll
            for (int fr = 0; fr < 4; fr++)
#pragma unroll
                for (int fc = 0; fc < 4; fc++)
                    mma_tf32(acc[fr][fc], a[fr], b[fc]);
        }
        __syncthreads();
    }

    // Epilogue: bias + store (float2 per c-frag half; cols even, NC even).
#pragma unroll
    for (int fr = 0; fr < 4; fr++) {
        int r0 = bm + wr + fr * 16 + g;
#pragma unroll
        for (int fc = 0; fc < 4; fc++) {
            int c = bn + wc + fc * 8 + tg * 2;
            if (c < NC) {
                float2 bb = *(const float2*)(bias + c);
                if (r0 < M) {
                    float2 o = make_float2(acc[fr][fc][0] + bb.x, acc[fr][fc][1] + bb.y);
                    *(float2*)(C + (size_t)r0 * NC + c) = o;
                }
                if (r0 + 8 < M) {
                    float2 o = make_float2(acc[fr][fc][2] + bb.x, acc[fr][fc][3] + bb.y);
                    *(float2*)(C + (size_t)(r0 + 8) * NC + c) = o;
                }
            }
        }
    }
}

// ---------------- edge kernels (warp per dst node, online softmax) ----------------
__device__ __forceinline__ float lrelu(float t) { return t > 0.f ? t : 0.2f * t; }
__device__ __forceinline__ float lrdot(float4 h, float4 d, float4 a) {
    return lrelu(h.x + d.x) * a.x + lrelu(h.y + d.y) * a.y +
           lrelu(h.z + d.z) * a.z + lrelu(h.w + d.w) * a.w;
}

__global__ void __launch_bounds__(256) gat_edge_d64(
    const float* __restrict__ hs, const float* __restrict__ hd,
    const float* __restrict__ attn, const float* __restrict__ res,
    float* __restrict__ xout, int N)
{
    int w = (blockIdx.x * blockDim.x + threadIdx.x) >> 5;
    if (w >= N) return;
    int lane = threadIdx.x & 31;
    int i1 = 4 * lane, i2 = 128 + 4 * lane;
    size_t nb = (size_t)w * 256;
    float4 a1 = *(const float4*)(attn + i1);
    float4 a2 = *(const float4*)(attn + i2);
    float4 d1 = *(const float4*)(hd + nb + i1);
    float4 d2 = *(const float4*)(hd + nb + i2);
    float m1 = -1e30f, s1 = 0.f, m2 = -1e30f, s2 = 0.f;
    float4 c1 = make_float4(0.f, 0.f, 0.f, 0.f);
    float4 c2 = make_float4(0.f, 0.f, 0.f, 0.f);
    int e0 = g_off[w], e1 = g_off[w + 1];
    for (int e = e0; e < e1; e++) {
        int sn = g_ssrc[e];
        const float* hp = hs + (size_t)sn * 256;
        float4 h1 = *(const float4*)(hp + i1);
        float4 h2 = *(const float4*)(hp + i2);
        float p1 = lrdot(h1, d1, a1);
        float p2 = lrdot(h2, d2, a2);
#pragma unroll
        for (int o = 8; o; o >>= 1) {
            p1 += __shfl_xor_sync(0xffffffffu, p1, o);
            p2 += __shfl_xor_sync(0xffffffffu, p2, o);
        }
        float nm = fmaxf(m1, p1);
        float sc = __expf(m1 - nm), wt = __expf(p1 - nm);
        s1 = s1 * sc + wt;
        c1.x = c1.x * sc + wt * h1.x; c1.y = c1.y * sc + wt * h1.y;
        c1.z = c1.z * sc + wt * h1.z; c1.w = c1.w * sc + wt * h1.w;
        m1 = nm;
        nm = fmaxf(m2, p2);
        sc = __expf(m2 - nm); wt = __expf(p2 - nm);
        s2 = s2 * sc + wt;
        c2.x = c2.x * sc + wt * h2.x; c2.y = c2.y * sc + wt * h2.y;
        c2.z = c2.z * sc + wt * h2.z; c2.w = c2.w * sc + wt * h2.w;
        m2 = nm;
    }
    float v1 = (s1 > 0.f) ? 1.f / s1 : 0.f;
    float v2 = (s2 > 0.f) ? 1.f / s2 : 0.f;
    float4 r1 = *(const float4*)(res + nb + i1);
    float4 r2 = *(const float4*)(res + nb + i2);
    float4 o1, o2;
    o1.x = c1.x * v1 + r1.x; o1.y = c1.y * v1 + r1.y;
    o1.z = c1.z * v1 + r1.z; o1.w = c1.w * v1 + r1.w;
    o2.x = c2.x * v2 + r2.x; o2.y = c2.y * v2 + r2.y;
    o2.z = c2.z * v2 + r2.z; o2.w = c2.w * v2 + r2.w;
    *(float4*)(xout + nb + i1) = o1;
    *(float4*)(xout + nb + i2) = o2;
}

__global__ void __launch_bounds__(256) gat_edge_d40(
    const float* __restrict__ hs, const float* __restrict__ hd,
    const float* __restrict__ attn, const float* __restrict__ res,
    float* __restrict__ out, int N)
{
    int w = (blockIdx.x * blockDim.x + threadIdx.x) >> 5;
    if (w >= N) return;
    int lane = threadIdx.x & 31;
    int h = lane >> 3;
    int d0 = (lane & 7) * 5;
    int idx = h * 40 + d0;
    float a[5], dv[5];
#pragma unroll
    for (int j = 0; j < 5; j++) {
        a[j] = attn[idx + j];
        dv[j] = hd[(size_t)w * 160 + idx + j];
    }
    float m = -1e30f, s = 0.f;
    float acc[5] = {0.f, 0.f, 0.f, 0.f, 0.f};
    int e0 = g_off[w], e1 = g_off[w + 1];
    for (int e = e0; e < e1; e++) {
        int sn = g_ssrc[e];
        const float* hp = hs + (size_t)sn * 160 + idx;
        float hv[5];
#pragma unroll
        for (int j = 0; j < 5; j++) hv[j] = hp[j];
        float p = 0.f;
#pragma unroll
        for (int j = 0; j < 5; j++) p += lrelu(hv[j] + dv[j]) * a[j];
#pragma unroll
        for (int o = 4; o; o >>= 1) p += __shfl_xor_sync(0xffffffffu, p, o);
        float nm = fmaxf(m, p);
        float sc = __expf(m - nm), wt = __expf(p - nm);
        s = s * sc + wt;
#pragma unroll
        for (int j = 0; j < 5; j++) acc[j] = acc[j] * sc + wt * hv[j];
        m = nm;
    }
    float inv = (s > 0.f) ? 1.f / s : 0.f;
    float v[5];
#pragma unroll
    for (int j = 0; j < 5; j++) v[j] = acc[j] * inv + res[(size_t)w * 160 + idx + j];
#pragma unroll
    for (int j = 0; j < 5; j++) {
        v[j] += __shfl_xor_sync(0xffffffffu, v[j], 8);
        v[j] += __shfl_xor_sync(0xffffffffu, v[j], 16);
    }
    if (lane < 8) {
#pragma unroll
        for (int j = 0; j < 5; j++) out[(size_t)w * 40 + d0 + j] = 0.25f * v[j];
    }
}

// ---------------- launch ----------------
extern "C" void kernel_launch(void* const* d_in, const int* in_sizes, int n_in,
                              void* d_out, int out_size)
{
    const float* x0  = (const float*)d_in[0];
    const int*   src = (const int*)d_in[1];
    const int*   dst = (const int*)d_in[2];
    const float* ws0 = (const float*)d_in[3];
    const float* bs0 = (const float*)d_in[4];
    const float* wd0 = (const float*)d_in[5];
    const float* bd0 = (const float*)d_in[6];
    const float* at0 = (const float*)d_in[7];
    const float* wr0 = (const float*)d_in[8];
    const float* br0 = (const float*)d_in[9];
    const float* ws1 = (const float*)d_in[10];
    const float* bs1 = (const float*)d_in[11];
    const float* wd1 = (const float*)d_in[12];
    const float* bd1 = (const float*)d_in[13];
    const float* at1 = (const float*)d_in[14];
    const float* ws2 = (const float*)d_in[15];
    const float* bs2 = (const float*)d_in[16];
    const float* wd2 = (const float*)d_in[17];
    const float* bd2 = (const float*)d_in[18];
    const float* at2 = (const float*)d_in[19];
    const float* wr2 = (const float*)d_in[20];
    const float* br2 = (const float*)d_in[21];
    float* out = (float*)d_out;

    const int N = NN, E = EE;

    float *hs, *hd, *res, *xA, *xB;
    cudaGetSymbolAddress((void**)&hs,  g_hs);
    cudaGetSymbolAddress((void**)&hd,  g_hd);
    cudaGetSymbolAddress((void**)&res, g_res);
    cudaGetSymbolAddress((void**)&xA,  g_xA);
    cudaGetSymbolAddress((void**)&xB,  g_xB);

    // CSR by dst
    k_zero<<<(N + 255) / 256, 256>>>(N);
    k_hist<<<(E + 255) / 256, 256>>>(dst, E);
    int NB = (N + 1023) / 1024;
    k_scan_reduce<<<NB, 1024>>>(N);
    k_scan_bsum<<<1, 1>>>(NB, N, E);
    k_scan_final<<<NB, 1024>>>(N);
    k_scatter<<<(E + 255) / 256, 256>>>(src, dst, E);

    const int MB = (N + 127) / 128;
    const int ewarps = (N * 32 + 255) / 256;

    // layer 0: K=128, NC=256, linear residual
    {
        dim3 g(MB, 2);
        gemm_tf32<<<g, 256>>>(x0, ws0, bs0, hs, N, 128, 256);
        gemm_tf32<<<g, 256>>>(x0, wd0, bd0, hd, N, 128, 256);
        gemm_tf32<<<g, 256>>>(x0, wr0, br0, res, N, 128, 256);
        gat_edge_d64<<<ewarps, 256>>>(hs, hd, at0, res, xA, N);
    }
    // layer 1: K=256, NC=256, identity residual (xA)
    {
        dim3 g(MB, 2);
        gemm_tf32<<<g, 256>>>(xA, ws1, bs1, hs, N, 256, 256);
        gemm_tf32<<<g, 256>>>(xA, wd1, bd1, hd, N, 256, 256);
        gat_edge_d64<<<ewarps, 256>>>(hs, hd, at1, xA, xB, N);
    }
    // layer 2: K=256, NC=160, linear residual, fused head-mean -> out
    {
        dim3 g(MB, 2);
        gemm_tf32<<<g, 256>>>(xB, ws2, bs2, hs, N, 256, 160);
        gemm_tf32<<<g, 256>>>(xB, wd2, bd2, hd, N, 256, 160);
        gemm_tf32<<<g, 256>>>(xB, wr2, br2, res, N, 256, 160);
        gat_edge_d40<<<ewarps, 256>>>(hs, hd, at2, res, out, N);
    }
}

// round 7
// speedup vs baseline: 1.9947x; 1.4705x over previous
#include <cuda_runtime.h>
#include <cuda_bf16.h>
#include <math.h>
#include <stdint.h>

// ---------------- problem constants ----------------
#define NN 50000
#define EE 400000

// weight split buffer offsets (elements): [NC][K] row-major per GEMM
#define WOFF_S0 0
#define WOFF_D0 (WOFF_S0 + 128*256)
#define WOFF_R0 (WOFF_D0 + 128*256)
#define WOFF_S1 (WOFF_R0 + 128*256)
#define WOFF_D1 (WOFF_S1 + 256*256)
#define WOFF_S2 (WOFF_D1 + 256*256)
#define WOFF_D2 (WOFF_S2 + 256*160)
#define WOFF_R2 (WOFF_D2 + 256*160)
#define WTOT    (WOFF_R2 + 256*160)

// ---------------- scratch (static device globals; 16B-aligned for cp.async) ----------------
__device__ float g_hs[NN * 256];
__device__ float g_hd[NN * 256];
__device__ float g_res[NN * 256];
__device__ float g_xA[NN * 256];
__device__ __align__(256) __nv_bfloat16 g_xhi[NN * 256];
__device__ __align__(256) __nv_bfloat16 g_xlo[NN * 256];
__device__ __align__(256) __nv_bfloat16 g_whi[WTOT];
__device__ __align__(256) __nv_bfloat16 g_wlo[WTOT];
__device__ int   g_deg[NN];
__device__ int   g_cur[NN];
__device__ int   g_off[NN + 1];
__device__ int   g_ssrc[EE];
__device__ int   g_bsum[64];

// ---------------- helpers ----------------
__device__ __forceinline__ uint32_t smem_to_u32(const void* p) {
    uint32_t a;
    asm("{ .reg .u64 t; cvta.to.shared.u64 t, %1; cvt.u32.u64 %0, t; }" : "=r"(a) : "l"(p));
    return a;
}
__device__ __forceinline__ void cp16(uint32_t saddr, const void* gaddr, int sz) {
    asm volatile("cp.async.cg.shared.global [%0], [%1], 16, %2;\n"
                 :: "r"(saddr), "l"(gaddr), "r"(sz));
}
__device__ __forceinline__ void cp_commit() {
    asm volatile("cp.async.commit_group;\n" ::: "memory");
}
template<int N> __device__ __forceinline__ void cp_wait() {
    asm volatile("cp.async.wait_group %0;\n" :: "n"(N) : "memory");
}
__device__ __forceinline__ uint32_t lds32(uint32_t addr) {
    uint32_t v;
    asm volatile("ld.shared.b32 %0, [%1];" : "=r"(v) : "r"(addr));
    return v;
}
__device__ __forceinline__ void mma_bf16(float* c, const uint32_t* a, uint32_t b0, uint32_t b1) {
    asm volatile(
        "mma.sync.aligned.m16n8k16.row.col.f32.bf16.bf16.f32 "
        "{%0,%1,%2,%3}, {%4,%5,%6,%7}, {%8,%9}, {%0,%1,%2,%3};\n"
        : "+f"(c[0]), "+f"(c[1]), "+f"(c[2]), "+f"(c[3])
        : "r"(a[0]), "r"(a[1]), "r"(a[2]), "r"(a[3]), "r"(b0), "r"(b1));
}

// ---------------- CSR build ----------------
__global__ void k_zero(int n) {
    int i = blockIdx.x * 256 + threadIdx.x;
    if (i < n) { g_deg[i] = 0; g_cur[i] = 0; }
}
__global__ void k_hist(const int* __restrict__ dst, int E) {
    int i = blockIdx.x * 256 + threadIdx.x;
    if (i < E) atomicAdd(&g_deg[dst[i]], 1);
}
__global__ void k_scan_reduce(int n) {
    __shared__ int sm[1024];
    int tid = threadIdx.x;
    int i = blockIdx.x * 1024 + tid;
    sm[tid] = (i < n) ? g_deg[i] : 0;
    __syncthreads();
    for (int st = 512; st > 0; st >>= 1) {
        if (tid < st) sm[tid] += sm[tid + st];
        __syncthreads();
    }
    if (tid == 0) g_bsum[blockIdx.x] = sm[0];
}
__global__ void k_scan_bsum(int nb, int n, int E) {
    int run = 0;
    for (int b = 0; b < nb; b++) { int t = g_bsum[b]; g_bsum[b] = run; run += t; }
    g_off[n] = E;
}
__global__ void k_scan_final(int n) {
    __shared__ int sm[1024];
    int tid = threadIdx.x;
    int i = blockIdx.x * 1024 + tid;
    int v = (i < n) ? g_deg[i] : 0;
    sm[tid] = v;
    __syncthreads();
    for (int st = 1; st < 1024; st <<= 1) {
        int t = (tid >= st) ? sm[tid - st] : 0;
        __syncthreads();
        sm[tid] += t;
        __syncthreads();
    }
    if (i < n) g_off[i] = g_bsum[blockIdx.x] + sm[tid] - v;
}
__global__ void k_scatter(const int* __restrict__ src, const int* __restrict__ dst, int E) {
    int i = blockIdx.x * 256 + threadIdx.x;
    if (i < E) {
        int d = dst[i];
        int p = g_off[d] + atomicAdd(&g_cur[d], 1);
        g_ssrc[p] = src[i];
    }
}

// ---------------- split / transpose prep ----------------
__global__ void k_xsplit(const float* __restrict__ X,
                         __nv_bfloat16* __restrict__ hi, __nv_bfloat16* __restrict__ lo, int n)
{
    int i = blockIdx.x * 256 + threadIdx.x;
    if (i < n) {
        float v = X[i];
        __nv_bfloat16 h = __float2bfloat16(v);
        hi[i] = h;
        lo[i] = __float2bfloat16(v - __bfloat162float(h));
    }
}
// W[K,NC] -> W'[n][k] = W[k][n], split hi/lo, row-major [NC][K] at offset woff.
__global__ void k_wsplit(const float* __restrict__ W, int K, int NC, int woff)
{
    int i = blockIdx.x * 256 + threadIdx.x;
    if (i < K * NC) {
        int n = i / K, k = i - n * K;
        float v = W[(size_t)k * NC + n];
        __nv_bfloat16 h = __float2bfloat16(v);
        g_whi[woff + i] = h;
        g_wlo[woff + i] = __float2bfloat16(v - __bfloat162float(h));
    }
}

// ---------------- bf16x3 mma.sync GEMM, cp.async double-buffered ----------------
// C[M,NC] = X @ W + bias via D += Ahi*Bhi + Ahi*Blo + Alo*Bhi.
// BM=128, BN=NFRAG*32 (128 or 160), BK=32. 8 warps: 2 (rows) x 4 (cols),
// warp tile 64 x NFRAG*8, mma m16n8k16 bf16.
// SMEM rows padded to 40 bf16 (80B = 20 banks -> conflict-free frag loads).
template<int NFRAG>
__global__ void __launch_bounds__(256, 1) gemm_bf16x3(
    const __nv_bfloat16* __restrict__ Ahi, const __nv_bfloat16* __restrict__ Alo,
    const __nv_bfloat16* __restrict__ WhiBase, const __nv_bfloat16* __restrict__ WloBase,
    int woff, const float* __restrict__ bias, float* __restrict__ C,
    int M, int K, int NC)
{
    extern __shared__ char smem[];
    constexpr int BN = NFRAG * 32;
    constexpr int szA = 128 * 80;       // bytes per A buffer (128 rows x 80B)
    constexpr int szB = BN * 80;
    constexpr int stageSz = 2 * szA + 2 * szB;

    const uint32_t sb = smem_to_u32(smem);
    const int tid  = threadIdx.x;
    const int lane = tid & 31;
    const int wid  = tid >> 5;
    const int wr   = (wid & 1) * 64;
    const int wc   = (wid >> 1) * (NFRAG * 8);
    const int bm   = blockIdx.x * 128;
    const int bn   = blockIdx.y * 128;   // only used when NFRAG==4 (NC=256)
    const int g    = lane >> 2;
    const int tg   = lane & 3;
    const __nv_bfloat16* __restrict__ Bhi = WhiBase + woff;
    const __nv_bfloat16* __restrict__ Blo = WloBase + woff;

    float acc[4][NFRAG][4];
#pragma unroll
    for (int i = 0; i < 4; i++)
#pragma unroll
        for (int j = 0; j < NFRAG; j++)
#pragma unroll
            for (int k = 0; k < 4; k++) acc[i][j][k] = 0.f;

    auto stage = [&](int s, int kofs) {
        uint32_t base = sb + s * stageSz;
        // A hi+lo: 128 rows x 32 bf16 = 4 x 16B chunks per row
#pragma unroll
        for (int i = tid; i < 512; i += 256) {
            int row = i >> 2, c = i & 3;
            uint32_t sa = base + row * 80 + c * 16;
            size_t go = (size_t)(bm + row) * K + kofs + c * 8;
            int sz = (bm + row < M) ? 16 : 0;
            cp16(sa, Ahi + go, sz);
            cp16(sa + szA, Alo + go, sz);
        }
        // B hi+lo: BN rows x 32 bf16 (all rows valid: NC tiles are exact)
        for (int i = tid; i < BN * 4; i += 256) {
            int row = i >> 2, c = i & 3;
            uint32_t sa = base + 2 * szA + row * 80 + c * 16;
            size_t go = (size_t)(bn + row) * K + kofs + c * 8;
            cp16(sa, Bhi + go, 16);
            cp16(sa + szB, Blo + go, 16);
        }
    };

    stage(0, 0);
    cp_commit();

    const int NKT = K >> 5;
    for (int kt = 0; kt < NKT; kt++) {
        if (kt + 1 < NKT) {
            stage((kt + 1) & 1, (kt + 1) * 32);
            cp_commit();
            cp_wait<1>();
        } else {
            cp_wait<0>();
        }
        __syncthreads();

        const uint32_t sAh = sb + (kt & 1) * stageSz;
        const uint32_t sAl = sAh + szA;
        const uint32_t sBh = sAh + 2 * szA;
        const uint32_t sBl = sBh + szB;
#pragma unroll
        for (int kc = 0; kc < 2; kc++) {
            const int kb = kc * 32;  // byte offset of 16-wide k-chunk
            uint32_t ah[4][4], al[4][4];
#pragma unroll
            for (int fr = 0; fr < 4; fr++) {
                uint32_t off = (uint32_t)(wr + fr * 16 + g) * 80 + kb + tg * 4;
                ah[fr][0] = lds32(sAh + off);
                ah[fr][1] = lds32(sAh + off + 640);
                ah[fr][2] = lds32(sAh + off + 16);
                ah[fr][3] = lds32(sAh + off + 656);
                al[fr][0] = lds32(sAl + off);
                al[fr][1] = lds32(sAl + off + 640);
                al[fr][2] = lds32(sAl + off + 16);
                al[fr][3] = lds32(sAl + off + 656);
            }
#pragma unroll
            for (int fc = 0; fc < NFRAG; fc++) {
                uint32_t off = (uint32_t)(wc + fc * 8 + g) * 80 + kb + tg * 4;
                uint32_t bh0 = lds32(sBh + off), bh1 = lds32(sBh + off + 16);
                uint32_t bl0 = lds32(sBl + off), bl1 = lds32(sBl + off + 16);
#pragma unroll
                for (int fr = 0; fr < 4; fr++) {
                    mma_bf16(acc[fr][fc], ah[fr], bh0, bh1);
                    mma_bf16(acc[fr][fc], ah[fr], bl0, bl1);
                    mma_bf16(acc[fr][fc], al[fr], bh0, bh1);
                }
            }
        }
        __syncthreads();
    }

    // epilogue: bias + float2 stores (C-frag: rows g,g+8; cols 2tg,2tg+1)
#pragma unroll
    for (int fr = 0; fr < 4; fr++) {
        int r0 = bm + wr + fr * 16 + g;
#pragma unroll
        for (int fc = 0; fc < NFRAG; fc++) {
            int c = bn + wc + fc * 8 + tg * 2;
            float2 bb = *(const float2*)(bias + c);
            if (r0 < M) {
                float2 o = make_float2(acc[fr][fc][0] + bb.x, acc[fr][fc][1] + bb.y);
                *(float2*)(C + (size_t)r0 * NC + c) = o;
            }
            if (r0 + 8 < M) {
                float2 o = make_float2(acc[fr][fc][2] + bb.x, acc[fr][fc][3] + bb.y);
                *(float2*)(C + (size_t)(r0 + 8) * NC + c) = o;
            }
        }
    }
}

// ---------------- edge kernels (warp per dst node, online softmax, 1-edge prefetch) ----------------
__device__ __forceinline__ float lrelu(float t) { return t > 0.f ? t : 0.2f * t; }
__device__ __forceinline__ float lrdot(float4 h, float4 d, float4 a) {
    return lrelu(h.x + d.x) * a.x + lrelu(h.y + d.y) * a.y +
           lrelu(h.z + d.z) * a.z + lrelu(h.w + d.w) * a.w;
}

__global__ void __launch_bounds__(256) gat_edge_d64(
    const float* __restrict__ hs, const float* __restrict__ hd,
    const float* __restrict__ attn, const float* __restrict__ res,
    float* __restrict__ xout,
    __nv_bfloat16* __restrict__ xhi, __nv_bfloat16* __restrict__ xlo, int N)
{
    int w = (blockIdx.x * blockDim.x + threadIdx.x) >> 5;
    if (w >= N) return;
    int lane = threadIdx.x & 31;
    int i1 = 4 * lane, i2 = 128 + 4 * lane;
    size_t nb = (size_t)w * 256;
    float4 a1 = *(const float4*)(attn + i1);
    float4 a2 = *(const float4*)(attn + i2);
    float4 d1 = *(const float4*)(hd + nb + i1);
    float4 d2 = *(const float4*)(hd + nb + i2);
    float m1 = -1e30f, s1 = 0.f, m2 = -1e30f, s2 = 0.f;
    float4 c1 = make_float4(0.f, 0.f, 0.f, 0.f);
    float4 c2 = make_float4(0.f, 0.f, 0.f, 0.f);
    int e0 = g_off[w], e1 = g_off[w + 1];
    float4 h1c, h2c;
    if (e0 < e1) {
        const float* hp = hs + (size_t)g_ssrc[e0] * 256;
        h1c = *(const float4*)(hp + i1);
        h2c = *(const float4*)(hp + i2);
    }
    for (int e = e0; e < e1; e++) {
        float4 h1 = h1c, h2 = h2c;
        if (e + 1 < e1) {
            const float* hp = hs + (size_t)g_ssrc[e + 1] * 256;
            h1c = *(const float4*)(hp + i1);
            h2c = *(const float4*)(hp + i2);
        }
        float p1 = lrdot(h1, d1, a1);
        float p2 = lrdot(h2, d2, a2);
#pragma unroll
        for (int o = 8; o; o >>= 1) {
            p1 += __shfl_xor_sync(0xffffffffu, p1, o);
            p2 += __shfl_xor_sync(0xffffffffu, p2, o);
        }
        float nm = fmaxf(m1, p1);
        float sc = __expf(m1 - nm), wt = __expf(p1 - nm);
        s1 = s1 * sc + wt;
        c1.x = c1.x * sc + wt * h1.x; c1.y = c1.y * sc + wt * h1.y;
        c1.z = c1.z * sc + wt * h1.z; c1.w = c1.w * sc + wt * h1.w;
        m1 = nm;
        nm = fmaxf(m2, p2);
        sc = __expf(m2 - nm); wt = __expf(p2 - nm);
        s2 = s2 * sc + wt;
        c2.x = c2.x * sc + wt * h2.x; c2.y = c2.y * sc + wt * h2.y;
        c2.z = c2.z * sc + wt * h2.z; c2.w = c2.w * sc + wt * h2.w;
        m2 = nm;
    }
    float v1 = (s1 > 0.f) ? 1.f / s1 : 0.f;
    float v2 = (s2 > 0.f) ? 1.f / s2 : 0.f;
    float4 r1 = *(const float4*)(res + nb + i1);
    float4 r2 = *(const float4*)(res + nb + i2);
    float o1[4], o2[4];
    o1[0] = c1.x * v1 + r1.x; o1[1] = c1.y * v1 + r1.y;
    o1[2] = c1.z * v1 + r1.z; o1[3] = c1.w * v1 + r1.w;
    o2[0] = c2.x * v2 + r2.x; o2[1] = c2.y * v2 + r2.y;
    o2[2] = c2.z * v2 + r2.z; o2[3] = c2.w * v2 + r2.w;
    if (xout) {
        *(float4*)(xout + nb + i1) = make_float4(o1[0], o1[1], o1[2], o1[3]);
        *(float4*)(xout + nb + i2) = make_float4(o2[0], o2[1], o2[2], o2[3]);
    }
#pragma unroll
    for (int j = 0; j < 4; j++) {
        __nv_bfloat16 h = __float2bfloat16(o1[j]);
        xhi[nb + i1 + j] = h;
        xlo[nb + i1 + j] = __float2bfloat16(o1[j] - __bfloat162float(h));
        h = __float2bfloat16(o2[j]);
        xhi[nb + i2 + j] = h;
        xlo[nb + i2 + j] = __float2bfloat16(o2[j] - __bfloat162float(h));
    }
}

__global__ void __launch_bounds__(256) gat_edge_d40(
    const float* __restrict__ hs, const float* __restrict__ hd,
    const float* __restrict__ attn, const float* __restrict__ res,
    float* __restrict__ out, int N)
{
    int w = (blockIdx.x * blockDim.x + threadIdx.x) >> 5;
    if (w >= N) return;
    int lane = threadIdx.x & 31;
    int h = lane >> 3;
    int d0 = (lane & 7) * 5;
    int idx = h * 40 + d0;
    float a[5], dv[5];
#pragma unroll
    for (int j = 0; j < 5; j++) {
        a[j] = attn[idx + j];
        dv[j] = hd[(size_t)w * 160 + idx + j];
    }
    float m = -1e30f, s = 0.f;
    float acc[5] = {0.f, 0.f, 0.f, 0.f, 0.f};
    int e0 = g_off[w], e1 = g_off[w + 1];
    float hc[5];
    if (e0 < e1) {
        const float* hp = hs + (size_t)g_ssrc[e0] * 160 + idx;
#pragma unroll
        for (int j = 0; j < 5; j++) hc[j] = hp[j];
    }
    for (int e = e0; e < e1; e++) {
        float hv[5];
#pragma unroll
        for (int j = 0; j < 5; j++) hv[j] = hc[j];
        if (e + 1 < e1) {
            const float* hp = hs + (size_t)g_ssrc[e + 1] * 160 + idx;
#pragma unroll
            for (int j = 0; j < 5; j++) hc[j] = hp[j];
        }
        float p = 0.f;
#pragma unroll
        for (int j = 0; j < 5; j++) p += lrelu(hv[j] + dv[j]) * a[j];
#pragma unroll
        for (int o = 4; o; o >>= 1) p += __shfl_xor_sync(0xffffffffu, p, o);
        float nm = fmaxf(m, p);
        float sc = __expf(m - nm), wt = __expf(p - nm);
        s = s * sc + wt;
#pragma unroll
        for (int j = 0; j < 5; j++) acc[j] = acc[j] * sc + wt * hv[j];
        m = nm;
    }
    float inv = (s > 0.f) ? 1.f / s : 0.f;
    float v[5];
#pragma unroll
    for (int j = 0; j < 5; j++) v[j] = acc[j] * inv + res[(size_t)w * 160 + idx + j];
#pragma unroll
    for (int j = 0; j < 5; j++) {
        v[j] += __shfl_xor_sync(0xffffffffu, v[j], 8);
        v[j] += __shfl_xor_sync(0xffffffffu, v[j], 16);
    }
    if (lane < 8) {
#pragma unroll
        for (int j = 0; j < 5; j++) out[(size_t)w * 40 + d0 + j] = 0.25f * v[j];
    }
}

// ---------------- launch ----------------
#define SMEM_G4 (2 * (2 * 128 * 80 + 2 * 128 * 80))   // 81920
#define SMEM_G5 (2 * (2 * 128 * 80 + 2 * 160 * 80))   // 92160

extern "C" void kernel_launch(void* const* d_in, const int* in_sizes, int n_in,
                              void* d_out, int out_size)
{
    const float* x0  = (const float*)d_in[0];
    const int*   src = (const int*)d_in[1];
    const int*   dst = (const int*)d_in[2];
    const float* ws0 = (const float*)d_in[3];
    const float* bs0 = (const float*)d_in[4];
    const float* wd0 = (const float*)d_in[5];
    const float* bd0 = (const float*)d_in[6];
    const float* at0 = (const float*)d_in[7];
    const float* wr0 = (const float*)d_in[8];
    const float* br0 = (const float*)d_in[9];
    const float* ws1 = (const float*)d_in[10];
    const float* bs1 = (const float*)d_in[11];
    const float* wd1 = (const float*)d_in[12];
    const float* bd1 = (const float*)d_in[13];
    const float* at1 = (const float*)d_in[14];
    const float* ws2 = (const float*)d_in[15];
    const float* bs2 = (const float*)d_in[16];
    const float* wd2 = (const float*)d_in[17];
    const float* bd2 = (const float*)d_in[18];
    const float* at2 = (const float*)d_in[19];
    const float* wr2 = (const float*)d_in[20];
    const float* br2 = (const float*)d_in[21];
    float* out = (float*)d_out;

    const int N = NN, E = EE;

    float *hs, *hd, *res, *xA;
    __nv_bfloat16 *xhi, *xlo, *whi, *wlo;
    cudaGetSymbolAddress((void**)&hs,  g_hs);
    cudaGetSymbolAddress((void**)&hd,  g_hd);
    cudaGetSymbolAddress((void**)&res, g_res);
    cudaGetSymbolAddress((void**)&xA,  g_xA);
    cudaGetSymbolAddress((void**)&xhi, g_xhi);
    cudaGetSymbolAddress((void**)&xlo, g_xlo);
    cudaGetSymbolAddress((void**)&whi, g_whi);
    cudaGetSymbolAddress((void**)&wlo, g_wlo);

    cudaFuncSetAttribute(gemm_bf16x3<4>, cudaFuncAttributeMaxDynamicSharedMemorySize, SMEM_G4);
    cudaFuncSetAttribute(gemm_bf16x3<5>, cudaFuncAttributeMaxDynamicSharedMemorySize, SMEM_G5);

    const int MB = (N + 127) / 128;
    const int ewarps = (N * 32 + 255) / 256;
    const dim3 g2(MB, 2);

    // ---- layer 0 prep + GEMMs first (so ncu -s 5 -c 1 lands on a GEMM) ----
    k_xsplit<<<(N * 128 + 255) / 256, 256>>>(x0, xhi, xlo, N * 128);
    k_wsplit<<<(128 * 256 + 255) / 256, 256>>>(ws0, 128, 256, WOFF_S0);
    k_wsplit<<<(128 * 256 + 255) / 256, 256>>>(wd0, 128, 256, WOFF_D0);
    gemm_bf16x3<4><<<g2, 256, SMEM_G4>>>(xhi, xlo, whi, wlo, WOFF_S0, bs0, hs, N, 128, 256);
    gemm_bf16x3<4><<<g2, 256, SMEM_G4>>>(xhi, xlo, whi, wlo, WOFF_D0, bd0, hd, N, 128, 256);
    k_wsplit<<<(128 * 256 + 255) / 256, 256>>>(wr0, 128, 256, WOFF_R0);
    gemm_bf16x3<4><<<g2, 256, SMEM_G4>>>(xhi, xlo, whi, wlo, WOFF_R0, br0, res, N, 128, 256);

    // ---- CSR by dst (needed before first edge kernel) ----
    k_zero<<<(N + 255) / 256, 256>>>(N);
    k_hist<<<(E + 255) / 256, 256>>>(dst, E);
    int NB = (N + 1023) / 1024;
    k_scan_reduce<<<NB, 1024>>>(N);
    k_scan_bsum<<<1, 1>>>(NB, N, E);
    k_scan_final<<<NB, 1024>>>(N);
    k_scatter<<<(E + 255) / 256, 256>>>(src, dst, E);

    gat_edge_d64<<<ewarps, 256>>>(hs, hd, at0, res, xA, xhi, xlo, N);

    // ---- layer 1: K=256, NC=256, identity residual ----
    k_wsplit<<<(256 * 256 + 255) / 256, 256>>>(ws1, 256, 256, WOFF_S1);
    k_wsplit<<<(256 * 256 + 255) / 256, 256>>>(wd1, 256, 256, WOFF_D1);
    gemm_bf16x3<4><<<g2, 256, SMEM_G4>>>(xhi, xlo, whi, wlo, WOFF_S1, bs1, hs, N, 256, 256);
    gemm_bf16x3<4><<<g2, 256, SMEM_G4>>>(xhi, xlo, whi, wlo, WOFF_D1, bd1, hd, N, 256, 256);
    gat_edge_d64<<<ewarps, 256>>>(hs, hd, at1, xA, nullptr, xhi, xlo, N);

    // ---- layer 2: K=256, NC=160 (BN=160, no padding), fused head-mean ----
    k_wsplit<<<(256 * 160 + 255) / 256, 256>>>(ws2, 256, 160, WOFF_S2);
    k_wsplit<<<(256 * 160 + 255) / 256, 256>>>(wd2, 256, 160, WOFF_D2);
    k_wsplit<<<(256 * 160 + 255) / 256, 256>>>(wr2, 256, 160, WOFF_R2);
    gemm_bf16x3<5><<<MB, 256, SMEM_G5>>>(xhi, xlo, whi, wlo, WOFF_S2, bs2, hs, N, 256, 160);
    gemm_bf16x3<5><<<MB, 256, SMEM_G5>>>(xhi, xlo, whi, wlo, WOFF_D2, bd2, hd, N, 256, 160);
    gemm_bf16x3<5><<<MB, 256, SMEM_G5>>>(xhi, xlo, whi, wlo, WOFF_R2, br2, res, N, 256, 160);
    gat_edge_d40<<<ewarps, 256>>>(hs, hd, at2, res, out, N);
}